// round 1
// baseline (speedup 1.0000x reference)
#include <cuda_runtime.h>
#include <cuda_bf16.h>

// FeatureVectorInteractions: B=4096, N=128, D=64
// out[b] = < sum_i clip(VI0[b,i],0,1)*V0[b,i,:], sum_j clip(VI1[b,j],0,1)*V1[b,j,:] >
//
// Pure HBM-streaming reduction. One CTA per batch, 256 threads.
// Thread t owns float4-column q=t%16 (d in [4q,4q+4)) and rows t/16 + 16*k.

#define NROW 128
#define NDIM 64
#define NF4  16          // float4s per row (64 floats / 4)
#define THREADS 256
#define ROWS_PER_THREAD 8  // 128 rows / 16 row-groups

__global__ __launch_bounds__(THREADS)
void fvi_kernel(const int* __restrict__ VI0,
                const int* __restrict__ VI1,
                const float4* __restrict__ V0,
                const float4* __restrict__ V1,
                float* __restrict__ out)
{
    const int b = blockIdx.x;
    const int t = threadIdx.x;

    __shared__ float sm0[NROW];
    __shared__ float sm1[NROW];
    __shared__ float4 s0[THREADS];
    __shared__ float4 s1[THREADS];
    __shared__ float sdot[2];

    // Load masks: clip(int, 0, 1) -> {0,1} float
    if (t < NROW) {
        int v = VI0[b * NROW + t];
        sm0[t] = (float)min(max(v, 0), 1);
    } else {
        int v = VI1[b * NROW + (t - NROW)];
        sm1[t - NROW] = (float)min(max(v, 0), 1);
    }
    __syncthreads();

    const int q  = t & (NF4 - 1);   // float4 column 0..15
    const int r0 = t >> 4;          // starting row 0..15

    const float4* p0 = V0 + (size_t)b * (NROW * NF4);
    const float4* p1 = V1 + (size_t)b * (NROW * NF4);

    float4 a0 = make_float4(0.f, 0.f, 0.f, 0.f);
    float4 a1 = make_float4(0.f, 0.f, 0.f, 0.f);

#pragma unroll
    for (int k = 0; k < ROWS_PER_THREAD; ++k) {
        const int row = r0 + k * 16;
        float4 x0 = p0[row * NF4 + q];
        float4 x1 = p1[row * NF4 + q];
        float m0 = sm0[row];
        float m1 = sm1[row];
        a0.x = fmaf(m0, x0.x, a0.x);
        a0.y = fmaf(m0, x0.y, a0.y);
        a0.z = fmaf(m0, x0.z, a0.z);
        a0.w = fmaf(m0, x0.w, a0.w);
        a1.x = fmaf(m1, x1.x, a1.x);
        a1.y = fmaf(m1, x1.y, a1.y);
        a1.z = fmaf(m1, x1.z, a1.z);
        a1.w = fmaf(m1, x1.w, a1.w);
    }

    s0[t] = a0;
    s1[t] = a1;
    __syncthreads();

    // Threads 0..63: reduce 16 row-group partials for dimension d=t,
    // then form u0[d]*u1[d].
    float prod = 0.f;
    if (t < NDIM) {
        const int qq = t >> 2;   // which float4 column
        const int j  = t & 3;    // element within float4
        float u0 = 0.f, u1 = 0.f;
#pragma unroll
        for (int g = 0; g < 16; ++g) {
            const float* f0 = (const float*)&s0[g * NF4 + qq];
            const float* f1 = (const float*)&s1[g * NF4 + qq];
            u0 += f0[j];
            u1 += f1[j];
        }
        prod = u0 * u1;
    }

    // Reduce 64 products: shfl within each of the two active warps, then combine.
    if (t < NDIM) {
#pragma unroll
        for (int off = 16; off > 0; off >>= 1)
            prod += __shfl_xor_sync(0xFFFFFFFFu, prod, off);
        if ((t & 31) == 0)
            sdot[t >> 5] = prod;
    }
    __syncthreads();

    if (t == 0)
        out[b] = sdot[0] + sdot[1];
}

extern "C" void kernel_launch(void* const* d_in, const int* in_sizes, int n_in,
                              void* d_out, int out_size)
{
    const int*    VI0 = (const int*)d_in[0];
    const int*    VI1 = (const int*)d_in[1];
    const float4* V0  = (const float4*)d_in[2];
    const float4* V1  = (const float4*)d_in[3];
    float*        out = (float*)d_out;

    const int B = in_sizes[0] / NROW;  // 4096
    fvi_kernel<<<B, THREADS>>>(VI0, VI1, V0, V1, out);
}